// round 8
// baseline (speedup 1.0000x reference)
#include <cuda_runtime.h>

// Adder2D: out[n,co,h,w] = -sum_{ci,kh,kw} |x_pad - w|
// Math per packed co-pair: FADD2 diff (fma) -> 64-bit sign-AND (2x LOP3, alu) -> FADD2 acc (fma).
// R8: R6 config + w loads vectorized as LDS.128 over tap-pairs (tap dim padded 9->10),
// cutting LDS slots (2.375->2.26 per contribution) and smem crossbar traffic ~22%.

#define CI_   64
#define CO_   64
#define H_    32
#define W_    32

#define CO_T     8     // co per block -> 4 packed pairs
#define C2_      (CO_T/2)
#define TILE_H   8     // output rows per block (thread owns rows py, py+4)
#define CI_Q     8     // ci per block (reduction split x8)
#define THREADS  128
#define TAP_PAD  10    // 9 taps padded to 10 for 16B-aligned pair loads

#define XS_ROWS (TILE_H + 2)   // 10
#define XS_COLS (W_ + 2)       // 34

typedef unsigned long long u64;

__device__ __forceinline__ u64 f2add(u64 a, u64 b) {
    u64 r;
    asm("add.rn.f32x2 %0, %1, %2;" : "=l"(r) : "l"(a), "l"(b));
    return r;
}

__device__ __forceinline__ u64 packff(float lo, float hi) {
    u64 r;
    asm("mov.b64 %0, {%1, %2};" : "=l"(r) : "f"(lo), "f"(hi));
    return r;
}

__device__ __forceinline__ float u64lo(u64 v) {
    return __uint_as_float((unsigned int)(v & 0xffffffffu));
}
__device__ __forceinline__ float u64hi(u64 v) {
    return __uint_as_float((unsigned int)(v >> 32));
}

__global__ void __launch_bounds__(THREADS, 9)
adder2d_kernel(const float* __restrict__ x,
               const float* __restrict__ w,
               float* __restrict__ out)
{
    // whole ci-slice x tile (halo incl.), each value duplicated in a u64: 21.8KB
    __shared__ u64 xs2[CI_Q][XS_ROWS][XS_COLS];
    // co-pair packed negated weights, tap dim padded to 10 (16B pair-aligned): 2.56KB
    __shared__ __align__(16) u64 ws2[C2_][CI_Q][TAP_PAD];

    const int tid = threadIdx.x;
    const int tx  = tid & 31;
    const int ty  = tid >> 5;
    const int h0  = blockIdx.x * TILE_H;
    const int co0 = blockIdx.y * CO_T;
    const int n   = blockIdx.z >> 3;
    const int ci0 = (blockIdx.z & 7) * CI_Q;

    // ---- stage w: negated + co-pair packed; tap 9 = padding (never used in math) ----
    for (int i = tid; i < C2_ * CI_Q * TAP_PAD; i += THREADS) {
        const int c2  = i / (CI_Q * TAP_PAD);
        const int j   = i - c2 * (CI_Q * TAP_PAD);
        const int cil = j / TAP_PAD;
        const int tap = j - cil * TAP_PAD;
        u64 v = 0ull;
        if (tap < 9) {
            const float w0 = w[(co0 + 2 * c2 + 0) * (CI_ * 9) + (ci0 + cil) * 9 + tap];
            const float w1 = w[(co0 + 2 * c2 + 1) * (CI_ * 9) + (ci0 + cil) * 9 + tap];
            v = packff(-w0, -w1);
        }
        (&ws2[0][0][0])[i] = v;
    }

    // ---- stage entire x slice (duplicated), exact-zero halo; div-free indexing ----
    const float* xn = x + (size_t)n * (CI_ * H_ * W_) + (size_t)ci0 * (H_ * W_);
    #pragma unroll
    for (int cl = 0; cl < CI_Q; ++cl) {
        const float* xc = xn + cl * (H_ * W_);
        for (int r = ty; r < XS_ROWS; r += 4) {
            const int gh = h0 + r - 1;
            const bool hok = (unsigned)gh < (unsigned)H_;
            for (int c = tx; c < XS_COLS; c += 32) {
                const int gw = c - 1;
                float v = 0.0f;
                if (hok && (unsigned)gw < (unsigned)W_)
                    v = xc[gh * W_ + gw];
                xs2[cl][r][c] = packff(v, v);
            }
        }
    }
    __syncthreads();

    // accumulators: [pixel(2)][co-pair(4)]
    u64 acc[2][C2_];
    #pragma unroll
    for (int p = 0; p < 2; ++p)
        #pragma unroll
        for (int c2 = 0; c2 < C2_; ++c2) acc[p][c2] = 0ull;

    const int px = tx;   // output column
    const int py = ty;   // owns rows py and py+4

    #pragma unroll 2
    for (int cl = 0; cl < CI_Q; ++cl) {
        #pragma unroll
        for (int tp = 0; tp < 5; ++tp) {           // tap pairs (0,1)(2,3)(4,5)(6,7)(8,-)
            const int t0 = 2 * tp;
            const int t1 = t0 + 1;                 // t1==9 on last pair: skipped (constant-folded)
            // x elements for tap t0 (both pixel rows)
            const u64 x00 = xs2[cl][py + 0 + t0 / 3][px + t0 % 3];
            const u64 x10 = xs2[cl][py + 4 + t0 / 3][px + t0 % 3];
            u64 x01 = 0, x11 = 0;
            if (t1 < 9) {
                x01 = xs2[cl][py + 0 + t1 / 3][px + t1 % 3];
                x11 = xs2[cl][py + 4 + t1 / 3][px + t1 % 3];
            }
            #pragma unroll
            for (int c2 = 0; c2 < C2_; ++c2) {
                // one LDS.128 fetches w for taps t0 and t1 (warp-uniform address)
                const ulonglong2 wv = *(const ulonglong2*)&ws2[c2][cl][t0];
                u64 d0 = f2add(x00, wv.x);              // fma pipe
                u64 d1 = f2add(x10, wv.x);
                d0 &= 0x7fffffff7fffffffULL;            // alu pipe (2x LOP3)
                d1 &= 0x7fffffff7fffffffULL;
                acc[0][c2] = f2add(acc[0][c2], d0);      // fma pipe
                acc[1][c2] = f2add(acc[1][c2], d1);
                if (t1 < 9) {
                    u64 e0 = f2add(x01, wv.y);
                    u64 e1 = f2add(x11, wv.y);
                    e0 &= 0x7fffffff7fffffffULL;
                    e1 &= 0x7fffffff7fffffffULL;
                    acc[0][c2] = f2add(acc[0][c2], e0);
                    acc[1][c2] = f2add(acc[1][c2], e1);
                }
            }
        }
    }

    // ---- epilogue: combine ci-slices via atomicAdd (out pre-zeroed) ----
    #pragma unroll
    for (int c2 = 0; c2 < C2_; ++c2) {
        #pragma unroll
        for (int p = 0; p < 2; ++p) {
            const float lo = u64lo(acc[p][c2]);
            const float hi = u64hi(acc[p][c2]);
            const int h = h0 + py + 4 * p;
            atomicAdd(&out[(((size_t)n * CO_ + (co0 + 2 * c2 + 0)) * H_ + h) * W_ + px], -lo);
            atomicAdd(&out[(((size_t)n * CO_ + (co0 + 2 * c2 + 1)) * H_ + h) * W_ + px], -hi);
        }
    }
}

extern "C" void kernel_launch(void* const* d_in, const int* in_sizes, int n_in,
                              void* d_out, int out_size)
{
    const float* x = (const float*)d_in[0];
    const float* w = (const float*)d_in[1];
    float* out = (float*)d_out;

    const int N = in_sizes[0] / (CI_ * H_ * W_);   // 16

    cudaMemsetAsync(d_out, 0, (size_t)out_size * sizeof(float));

    dim3 grid(H_ / TILE_H, CO_ / CO_T, N * 8);     // (4, 8, 128) = 4096 blocks
    adder2d_kernel<<<grid, THREADS>>>(x, w, out);
}

// round 9
// speedup vs baseline: 1.0071x; 1.0071x over previous
#include <cuda_runtime.h>

// Adder2D: out[n,co,h,w] = -sum_{ci,kh,kw} |x_pad - w|
// Math per packed co-pair: FADD2 diff (fma) -> 64-bit sign-AND (2x LOP3, alu) -> FADD2 acc (fma).
// R9 = R6 skeleton + two LDS cuts:
//   (1) ws2 relaid as [cl][tap][c2] -> per (cl,tap) two uniform LDS.128 fetch all 4 co-pairs
//   (2) pixels are ADJACENT rows {2ty, 2ty+1} -> x rows 2ty..2ty+3 loaded once per (cl,kw),
//       shared across kh (CSE), 12 x-loads/cl instead of 18.

#define CI_   64
#define CO_   64
#define H_    32
#define W_    32

#define CO_T     8     // co per block -> 4 packed pairs
#define C2_      (CO_T/2)
#define TILE_H   8     // output rows per block; thread owns rows 2ty, 2ty+1
#define CI_Q     8     // ci per block (reduction split x8)
#define THREADS  128

#define XS_ROWS (TILE_H + 2)   // 10
#define XS_COLS (W_ + 2)       // 34

typedef unsigned long long u64;

__device__ __forceinline__ u64 f2add(u64 a, u64 b) {
    u64 r;
    asm("add.rn.f32x2 %0, %1, %2;" : "=l"(r) : "l"(a), "l"(b));
    return r;
}

__device__ __forceinline__ u64 packff(float lo, float hi) {
    u64 r;
    asm("mov.b64 %0, {%1, %2};" : "=l"(r) : "f"(lo), "f"(hi));
    return r;
}

__device__ __forceinline__ float u64lo(u64 v) {
    return __uint_as_float((unsigned int)(v & 0xffffffffu));
}
__device__ __forceinline__ float u64hi(u64 v) {
    return __uint_as_float((unsigned int)(v >> 32));
}

__global__ void __launch_bounds__(THREADS, 9)
adder2d_kernel(const float* __restrict__ x,
               const float* __restrict__ w,
               float* __restrict__ out)
{
    // whole ci-slice x tile (halo incl.), each value duplicated in a u64: 21.8KB
    __shared__ u64 xs2[CI_Q][XS_ROWS][XS_COLS];
    // negated co-pair packed weights, c2 contiguous & 16B aligned: [cl][tap][c2], 2.3KB
    __shared__ __align__(16) u64 ws2[CI_Q][9][C2_];

    const int tid = threadIdx.x;
    const int tx  = tid & 31;
    const int ty  = tid >> 5;
    const int h0  = blockIdx.x * TILE_H;
    const int co0 = blockIdx.y * CO_T;
    const int n   = blockIdx.z >> 3;
    const int ci0 = (blockIdx.z & 7) * CI_Q;

    // ---- stage w: negated + co-pair packed, layout [cl][tap][c2] ----
    for (int i = tid; i < CI_Q * 9 * C2_; i += THREADS) {
        const int cl  = i / (9 * C2_);
        const int j   = i - cl * (9 * C2_);
        const int tap = j / C2_;
        const int c2  = j - tap * C2_;
        const float w0 = w[(co0 + 2 * c2 + 0) * (CI_ * 9) + (ci0 + cl) * 9 + tap];
        const float w1 = w[(co0 + 2 * c2 + 1) * (CI_ * 9) + (ci0 + cl) * 9 + tap];
        (&ws2[0][0][0])[i] = packff(-w0, -w1);
    }

    // ---- stage entire x slice (duplicated), exact-zero halo; div-free indexing ----
    const float* xn = x + (size_t)n * (CI_ * H_ * W_) + (size_t)ci0 * (H_ * W_);
    #pragma unroll
    for (int cl = 0; cl < CI_Q; ++cl) {
        const float* xc = xn + cl * (H_ * W_);
        for (int r = ty; r < XS_ROWS; r += 4) {
            const int gh = h0 + r - 1;
            const bool hok = (unsigned)gh < (unsigned)H_;
            for (int c = tx; c < XS_COLS; c += 32) {
                const int gw = c - 1;
                float v = 0.0f;
                if (hok && (unsigned)gw < (unsigned)W_)
                    v = xc[gh * W_ + gw];
                xs2[cl][r][c] = packff(v, v);
            }
        }
    }
    __syncthreads();

    // accumulators: [pixel-row(2)][co-pair(4)]; pixel rows are 2ty and 2ty+1
    u64 acc[2][C2_];
    #pragma unroll
    for (int p = 0; p < 2; ++p)
        #pragma unroll
        for (int c2 = 0; c2 < C2_; ++c2) acc[p][c2] = 0ull;

    const int px = tx;        // output column
    const int ry = 2 * ty;    // first owned output row within tile

    #pragma unroll 2
    for (int cl = 0; cl < CI_Q; ++cl) {
        #pragma unroll
        for (int kw = 0; kw < 3; ++kw) {
            // the 4 x rows serving both pixel rows across all kh (loaded once, CSE'd)
            u64 xr[4];
            #pragma unroll
            for (int r = 0; r < 4; ++r)
                xr[r] = xs2[cl][ry + r][px + kw];          // LDS.64
            #pragma unroll
            for (int kh = 0; kh < 3; ++kh) {
                const int tap = kh * 3 + kw;
                // two uniform LDS.128 fetch all 4 co-pairs for this tap
                const ulonglong2 wv01 = *(const ulonglong2*)&ws2[cl][tap][0];
                const ulonglong2 wv23 = *(const ulonglong2*)&ws2[cl][tap][2];
                const u64 wp[4] = { wv01.x, wv01.y, wv23.x, wv23.y };
                #pragma unroll
                for (int c2 = 0; c2 < C2_; ++c2) {
                    u64 d0 = f2add(xr[kh + 0], wp[c2]);     // fma pipe
                    u64 d1 = f2add(xr[kh + 1], wp[c2]);
                    d0 &= 0x7fffffff7fffffffULL;            // alu pipe (2x LOP3)
                    d1 &= 0x7fffffff7fffffffULL;
                    acc[0][c2] = f2add(acc[0][c2], d0);      // fma pipe
                    acc[1][c2] = f2add(acc[1][c2], d1);
                }
            }
        }
    }

    // ---- epilogue: combine ci-slices via atomicAdd (out pre-zeroed) ----
    #pragma unroll
    for (int c2 = 0; c2 < C2_; ++c2) {
        #pragma unroll
        for (int p = 0; p < 2; ++p) {
            const float lo = u64lo(acc[p][c2]);
            const float hi = u64hi(acc[p][c2]);
            const int h = h0 + ry + p;
            atomicAdd(&out[(((size_t)n * CO_ + (co0 + 2 * c2 + 0)) * H_ + h) * W_ + px], -lo);
            atomicAdd(&out[(((size_t)n * CO_ + (co0 + 2 * c2 + 1)) * H_ + h) * W_ + px], -hi);
        }
    }
}

extern "C" void kernel_launch(void* const* d_in, const int* in_sizes, int n_in,
                              void* d_out, int out_size)
{
    const float* x = (const float*)d_in[0];
    const float* w = (const float*)d_in[1];
    float* out = (float*)d_out;

    const int N = in_sizes[0] / (CI_ * H_ * W_);   // 16

    cudaMemsetAsync(d_out, 0, (size_t)out_size * sizeof(float));

    dim3 grid(H_ / TILE_H, CO_ / CO_T, N * 8);     // (4, 8, 128) = 4096 blocks
    adder2d_kernel<<<grid, THREADS>>>(x, w, out);
}

// round 10
// speedup vs baseline: 1.0275x; 1.0202x over previous
#include <cuda_runtime.h>

// Adder2D: out[n,co,h,w] = -sum_{ci,kh,kw} |x_pad - w|
// Math per packed co-pair: FADD2 diff (fma) -> 64-bit sign-AND (2x LOP3, alu) -> FADD2 acc (fma).
// R10 = R6 schedule EXACTLY (loads interleaved in tap/c2 loops), two slot cuts only:
//   (1) adjacent pixel rows (ry, ry+1) -> x loads CSE across kh: 18 -> 12 unique LDS.64/cl
//   (2) w c2-paired LDS.128 loaded inside the c2 loop (position preserved): 36 -> 18 slots/cl

#define CI_   64
#define CO_   64
#define H_    32
#define W_    32

#define CO_T     8     // co per block -> 4 packed pairs
#define C2_      (CO_T/2)
#define TILE_H   8     // output rows per block; thread owns rows 2ty, 2ty+1
#define CI_Q     8     // ci per block (reduction split x8)
#define THREADS  128

#define XS_ROWS (TILE_H + 2)   // 10
#define XS_COLS (W_ + 2)       // 34

typedef unsigned long long u64;

__device__ __forceinline__ u64 f2add(u64 a, u64 b) {
    u64 r;
    asm("add.rn.f32x2 %0, %1, %2;" : "=l"(r) : "l"(a), "l"(b));
    return r;
}

__device__ __forceinline__ u64 packff(float lo, float hi) {
    u64 r;
    asm("mov.b64 %0, {%1, %2};" : "=l"(r) : "f"(lo), "f"(hi));
    return r;
}

__device__ __forceinline__ float u64lo(u64 v) {
    return __uint_as_float((unsigned int)(v & 0xffffffffu));
}
__device__ __forceinline__ float u64hi(u64 v) {
    return __uint_as_float((unsigned int)(v >> 32));
}

__global__ void __launch_bounds__(THREADS, 9)
adder2d_kernel(const float* __restrict__ x,
               const float* __restrict__ w,
               float* __restrict__ out)
{
    // whole ci-slice x tile (halo incl.), each value duplicated in a u64: 21.8KB
    __shared__ u64 xs2[CI_Q][XS_ROWS][XS_COLS];
    // negated co-pair packed weights, c2 contiguous & 16B aligned: [cl][tap][c2], 2.3KB
    __shared__ __align__(16) u64 ws2[CI_Q][9][C2_];

    const int tid = threadIdx.x;
    const int tx  = tid & 31;
    const int ty  = tid >> 5;
    const int h0  = blockIdx.x * TILE_H;
    const int co0 = blockIdx.y * CO_T;
    const int n   = blockIdx.z >> 3;
    const int ci0 = (blockIdx.z & 7) * CI_Q;

    // ---- stage w: negated + co-pair packed, layout [cl][tap][c2] ----
    for (int i = tid; i < CI_Q * 9 * C2_; i += THREADS) {
        const int cl  = i / (9 * C2_);
        const int j   = i - cl * (9 * C2_);
        const int tap = j / C2_;
        const int c2  = j - tap * C2_;
        const float w0 = w[(co0 + 2 * c2 + 0) * (CI_ * 9) + (ci0 + cl) * 9 + tap];
        const float w1 = w[(co0 + 2 * c2 + 1) * (CI_ * 9) + (ci0 + cl) * 9 + tap];
        (&ws2[0][0][0])[i] = packff(-w0, -w1);
    }

    // ---- stage entire x slice (duplicated), exact-zero halo; div-free indexing ----
    const float* xn = x + (size_t)n * (CI_ * H_ * W_) + (size_t)ci0 * (H_ * W_);
    #pragma unroll
    for (int cl = 0; cl < CI_Q; ++cl) {
        const float* xc = xn + cl * (H_ * W_);
        for (int r = ty; r < XS_ROWS; r += 4) {
            const int gh = h0 + r - 1;
            const bool hok = (unsigned)gh < (unsigned)H_;
            for (int c = tx; c < XS_COLS; c += 32) {
                const int gw = c - 1;
                float v = 0.0f;
                if (hok && (unsigned)gw < (unsigned)W_)
                    v = xc[gh * W_ + gw];
                xs2[cl][r][c] = packff(v, v);
            }
        }
    }
    __syncthreads();

    // accumulators: [pixel-row(2)][co-pair(4)]; pixel rows are 2ty and 2ty+1
    u64 acc[2][C2_];
    #pragma unroll
    for (int p = 0; p < 2; ++p)
        #pragma unroll
        for (int c2 = 0; c2 < C2_; ++c2) acc[p][c2] = 0ull;

    const int px = tx;        // output column
    const int ry = 2 * ty;    // first owned output row within tile

    #pragma unroll 2
    for (int cl = 0; cl < CI_Q; ++cl) {
        #pragma unroll
        for (int kh = 0; kh < 3; ++kh) {
            #pragma unroll
            for (int kw = 0; kw < 3; ++kw) {
                // adjacent rows: these addresses repeat across kh -> ptxas CSEs the LDS
                const u64 x0 = xs2[cl][ry + 0 + kh][px + kw];   // LDS.64
                const u64 x1 = xs2[cl][ry + 1 + kh][px + kw];   // LDS.64 (== next kh's x0)
                const int tap = kh * 3 + kw;
                #pragma unroll
                for (int cp = 0; cp < C2_ / 2; ++cp) {
                    // one uniform LDS.128 fetches two co-pairs, loaded HERE (interleaved)
                    const ulonglong2 wv = *(const ulonglong2*)&ws2[cl][tap][2 * cp];
                    u64 d0 = f2add(x0, wv.x);               // fma pipe
                    u64 d1 = f2add(x1, wv.x);
                    d0 &= 0x7fffffff7fffffffULL;            // alu pipe (2x LOP3)
                    d1 &= 0x7fffffff7fffffffULL;
                    acc[0][2 * cp + 0] = f2add(acc[0][2 * cp + 0], d0);
                    acc[1][2 * cp + 0] = f2add(acc[1][2 * cp + 0], d1);
                    u64 e0 = f2add(x0, wv.y);
                    u64 e1 = f2add(x1, wv.y);
                    e0 &= 0x7fffffff7fffffffULL;
                    e1 &= 0x7fffffff7fffffffULL;
                    acc[0][2 * cp + 1] = f2add(acc[0][2 * cp + 1], e0);
                    acc[1][2 * cp + 1] = f2add(acc[1][2 * cp + 1], e1);
                }
            }
        }
    }

    // ---- epilogue: combine ci-slices via atomicAdd (out pre-zeroed) ----
    #pragma unroll
    for (int c2 = 0; c2 < C2_; ++c2) {
        #pragma unroll
        for (int p = 0; p < 2; ++p) {
            const float lo = u64lo(acc[p][c2]);
            const float hi = u64hi(acc[p][c2]);
            const int h = h0 + ry + p;
            atomicAdd(&out[(((size_t)n * CO_ + (co0 + 2 * c2 + 0)) * H_ + h) * W_ + px], -lo);
            atomicAdd(&out[(((size_t)n * CO_ + (co0 + 2 * c2 + 1)) * H_ + h) * W_ + px], -hi);
        }
    }
}

extern "C" void kernel_launch(void* const* d_in, const int* in_sizes, int n_in,
                              void* d_out, int out_size)
{
    const float* x = (const float*)d_in[0];
    const float* w = (const float*)d_in[1];
    float* out = (float*)d_out;

    const int N = in_sizes[0] / (CI_ * H_ * W_);   // 16

    cudaMemsetAsync(d_out, 0, (size_t)out_size * sizeof(float));

    dim3 grid(H_ / TILE_H, CO_ / CO_T, N * 8);     // (4, 8, 128) = 4096 blocks
    adder2d_kernel<<<grid, THREADS>>>(x, w, out);
}

// round 11
// speedup vs baseline: 1.0583x; 1.0300x over previous
#include <cuda_runtime.h>

// Adder2D: out[n,co,h,w] = -sum_{ci,kh,kw} |x_pad - w|
// R11: CI-PACKING. u64 = (x[ci_even], x[ci_odd]); FADD2 diff (fma) -> sign-AND (2x LOP3, alu)
// -> FADD2 acc (fma) computes two ci-contributions at once. Accumulators horizontally
// summed (lo+hi) in the epilogue. Halves x smem (no duplication) and x LDS count.

#define CI_   64
#define CO_   64
#define H_    32
#define W_    32

#define CO_T     4     // co per block (scalar co, ci packed instead)
#define TILE_H   8     // output rows per block; thread owns rows 2ty, 2ty+1
#define CI_Q     8     // ci per block -> 4 packed ci-pairs (reduction split x8)
#define Q_       (CI_Q/2)
#define THREADS  128

#define XS_ROWS (TILE_H + 2)   // 10
#define XS_COLS (W_ + 2)       // 34

typedef unsigned long long u64;

__device__ __forceinline__ u64 f2add(u64 a, u64 b) {
    u64 r;
    asm("add.rn.f32x2 %0, %1, %2;" : "=l"(r) : "l"(a), "l"(b));
    return r;
}

__device__ __forceinline__ u64 packff(float lo, float hi) {
    u64 r;
    asm("mov.b64 %0, {%1, %2};" : "=l"(r) : "f"(lo), "f"(hi));
    return r;
}

__device__ __forceinline__ float u64lo(u64 v) {
    return __uint_as_float((unsigned int)(v & 0xffffffffu));
}
__device__ __forceinline__ float u64hi(u64 v) {
    return __uint_as_float((unsigned int)(v >> 32));
}

__global__ void __launch_bounds__(THREADS, 10)
adder2d_kernel(const float* __restrict__ x,
               const float* __restrict__ w,
               float* __restrict__ out)
{
    // ci-pair packed x tile (halo incl.): 4 planes x 10 x 34 x 8B = 10.9KB
    __shared__ u64 xs2[Q_][XS_ROWS][XS_COLS];
    // ci-pair packed negated weights, co contiguous & 16B aligned: [q][tap][co], 1.2KB
    __shared__ __align__(16) u64 ws2[Q_][9][CO_T];

    const int tid = threadIdx.x;
    const int tx  = tid & 31;
    const int ty  = tid >> 5;
    const int h0  = blockIdx.x * TILE_H;
    const int co0 = blockIdx.y * CO_T;
    const int n   = blockIdx.z >> 3;
    const int ci0 = (blockIdx.z & 7) * CI_Q;

    // ---- stage w: negated + ci-pair packed, layout [q][tap][co] ----
    for (int i = tid; i < Q_ * 9 * CO_T; i += THREADS) {
        const int q   = i / (9 * CO_T);
        const int j   = i - q * (9 * CO_T);
        const int tap = j / CO_T;
        const int co  = j - tap * CO_T;
        const float w0 = w[(co0 + co) * (CI_ * 9) + (ci0 + 2 * q + 0) * 9 + tap];
        const float w1 = w[(co0 + co) * (CI_ * 9) + (ci0 + 2 * q + 1) * 9 + tap];
        (&ws2[0][0][0])[i] = packff(-w0, -w1);
    }

    // ---- stage x: pack adjacent ci planes, exact-zero halo; div-free indexing ----
    const float* xn = x + (size_t)n * (CI_ * H_ * W_) + (size_t)ci0 * (H_ * W_);
    #pragma unroll
    for (int q = 0; q < Q_; ++q) {
        const float* xe = xn + (2 * q + 0) * (H_ * W_);
        const float* xo = xn + (2 * q + 1) * (H_ * W_);
        for (int r = ty; r < XS_ROWS; r += 4) {
            const int gh = h0 + r - 1;
            const bool hok = (unsigned)gh < (unsigned)H_;
            for (int c = tx; c < XS_COLS; c += 32) {
                const int gw = c - 1;
                float ve = 0.0f, vo = 0.0f;
                if (hok && (unsigned)gw < (unsigned)W_) {
                    ve = xe[gh * W_ + gw];
                    vo = xo[gh * W_ + gw];
                }
                xs2[q][r][c] = packff(ve, vo);
            }
        }
    }
    __syncthreads();

    // accumulators: [pixel-row(2)][co(4)]; halves hold even/odd ci partial sums
    u64 acc[2][CO_T];
    #pragma unroll
    for (int p = 0; p < 2; ++p)
        #pragma unroll
        for (int co = 0; co < CO_T; ++co) acc[p][co] = 0ull;

    const int px = tx;        // output column
    const int ry = 2 * ty;    // first owned output row within tile

    #pragma unroll 2
    for (int q = 0; q < Q_; ++q) {
        #pragma unroll
        for (int kh = 0; kh < 3; ++kh) {
            #pragma unroll
            for (int kw = 0; kw < 3; ++kw) {
                // adjacent rows: addresses repeat across kh -> ptxas CSEs the LDS
                const u64 x0 = xs2[q][ry + 0 + kh][px + kw];   // LDS.64 (2 ci)
                const u64 x1 = xs2[q][ry + 1 + kh][px + kw];
                const int tap = kh * 3 + kw;
                #pragma unroll
                for (int cp = 0; cp < CO_T / 2; ++cp) {
                    // one uniform LDS.128 fetches w for two co (each packed over ci-pair)
                    const ulonglong2 wv = *(const ulonglong2*)&ws2[q][tap][2 * cp];
                    u64 d0 = f2add(x0, wv.x);               // fma pipe
                    u64 d1 = f2add(x1, wv.x);
                    d0 &= 0x7fffffff7fffffffULL;            // alu pipe (2x LOP3)
                    d1 &= 0x7fffffff7fffffffULL;
                    acc[0][2 * cp + 0] = f2add(acc[0][2 * cp + 0], d0);
                    acc[1][2 * cp + 0] = f2add(acc[1][2 * cp + 0], d1);
                    u64 e0 = f2add(x0, wv.y);
                    u64 e1 = f2add(x1, wv.y);
                    e0 &= 0x7fffffff7fffffffULL;
                    e1 &= 0x7fffffff7fffffffULL;
                    acc[0][2 * cp + 1] = f2add(acc[0][2 * cp + 1], e0);
                    acc[1][2 * cp + 1] = f2add(acc[1][2 * cp + 1], e1);
                }
            }
        }
    }

    // ---- epilogue: horizontal add (even-ci + odd-ci), atomic combine (out pre-zeroed) ----
    #pragma unroll
    for (int co = 0; co < CO_T; ++co) {
        #pragma unroll
        for (int p = 0; p < 2; ++p) {
            const float s = u64lo(acc[p][co]) + u64hi(acc[p][co]);
            const int h = h0 + ry + p;
            atomicAdd(&out[(((size_t)n * CO_ + (co0 + co)) * H_ + h) * W_ + px], -s);
        }
    }
}

extern "C" void kernel_launch(void* const* d_in, const int* in_sizes, int n_in,
                              void* d_out, int out_size)
{
    const float* x = (const float*)d_in[0];
    const float* w = (const float*)d_in[1];
    float* out = (float*)d_out;

    const int N = in_sizes[0] / (CI_ * H_ * W_);   // 16

    cudaMemsetAsync(d_out, 0, (size_t)out_size * sizeof(float));

    dim3 grid(H_ / TILE_H, CO_ / CO_T, N * 8);     // (4, 16, 128) = 8192 blocks
    adder2d_kernel<<<grid, THREADS>>>(x, w, out);
}

// round 12
// speedup vs baseline: 1.1927x; 1.1270x over previous
#include <cuda_runtime.h>

// Adder2D: out[n,co,h,w] = -sum_{ci,kh,kw} |x_pad - w|
// R12 = R11 (ci-packing: u64 = (x[ci_e], x[ci_o]); FADD2 diff -> 2xLOP3 abs -> FADD2 acc)
// with CO_T=8: staged x feeds 8 output channels, halving staging/barrier overhead fraction.
// Floor: 4 issue slots per 2 contributions (dual-pipe fma/alu), ~2.17 incl. LDS.

#define CI_   64
#define CO_   64
#define H_    32
#define W_    32

#define CO_T     8     // co per block (scalar co; ci packed)
#define TILE_H   8     // output rows per block; thread owns rows 2ty, 2ty+1
#define CI_Q     8     // ci per block -> 4 packed ci-pairs (reduction split x8)
#define Q_       (CI_Q/2)
#define THREADS  128

#define XS_ROWS (TILE_H + 2)   // 10
#define XS_COLS (W_ + 2)       // 34

typedef unsigned long long u64;

__device__ __forceinline__ u64 f2add(u64 a, u64 b) {
    u64 r;
    asm("add.rn.f32x2 %0, %1, %2;" : "=l"(r) : "l"(a), "l"(b));
    return r;
}

__device__ __forceinline__ u64 packff(float lo, float hi) {
    u64 r;
    asm("mov.b64 %0, {%1, %2};" : "=l"(r) : "f"(lo), "f"(hi));
    return r;
}

__device__ __forceinline__ float u64lo(u64 v) {
    return __uint_as_float((unsigned int)(v & 0xffffffffu));
}
__device__ __forceinline__ float u64hi(u64 v) {
    return __uint_as_float((unsigned int)(v >> 32));
}

__global__ void __launch_bounds__(THREADS, 8)
adder2d_kernel(const float* __restrict__ x,
               const float* __restrict__ w,
               float* __restrict__ out)
{
    // ci-pair packed x tile (halo incl.): 4 planes x 10 x 34 x 8B = 10.9KB
    __shared__ u64 xs2[Q_][XS_ROWS][XS_COLS];
    // ci-pair packed negated weights, co contiguous & 16B aligned: [q][tap][co], 2.3KB
    __shared__ __align__(16) u64 ws2[Q_][9][CO_T];

    const int tid = threadIdx.x;
    const int tx  = tid & 31;
    const int ty  = tid >> 5;
    const int h0  = blockIdx.x * TILE_H;
    const int co0 = blockIdx.y * CO_T;
    const int n   = blockIdx.z >> 3;
    const int ci0 = (blockIdx.z & 7) * CI_Q;

    // ---- stage w: negated + ci-pair packed, layout [q][tap][co] ----
    for (int i = tid; i < Q_ * 9 * CO_T; i += THREADS) {
        const int q   = i / (9 * CO_T);
        const int j   = i - q * (9 * CO_T);
        const int tap = j / CO_T;
        const int co  = j - tap * CO_T;
        const float w0 = w[(co0 + co) * (CI_ * 9) + (ci0 + 2 * q + 0) * 9 + tap];
        const float w1 = w[(co0 + co) * (CI_ * 9) + (ci0 + 2 * q + 1) * 9 + tap];
        (&ws2[0][0][0])[i] = packff(-w0, -w1);
    }

    // ---- stage x: pack adjacent ci planes, exact-zero halo; div-free indexing ----
    const float* xn = x + (size_t)n * (CI_ * H_ * W_) + (size_t)ci0 * (H_ * W_);
    #pragma unroll
    for (int q = 0; q < Q_; ++q) {
        const float* xe = xn + (2 * q + 0) * (H_ * W_);
        const float* xo = xn + (2 * q + 1) * (H_ * W_);
        for (int r = ty; r < XS_ROWS; r += 4) {
            const int gh = h0 + r - 1;
            const bool hok = (unsigned)gh < (unsigned)H_;
            for (int c = tx; c < XS_COLS; c += 32) {
                const int gw = c - 1;
                float ve = 0.0f, vo = 0.0f;
                if (hok && (unsigned)gw < (unsigned)W_) {
                    ve = xe[gh * W_ + gw];
                    vo = xo[gh * W_ + gw];
                }
                xs2[q][r][c] = packff(ve, vo);
            }
        }
    }
    __syncthreads();

    // accumulators: [pixel-row(2)][co(8)]; halves hold even/odd ci partial sums
    u64 acc[2][CO_T];
    #pragma unroll
    for (int p = 0; p < 2; ++p)
        #pragma unroll
        for (int co = 0; co < CO_T; ++co) acc[p][co] = 0ull;

    const int px = tx;        // output column
    const int ry = 2 * ty;    // first owned output row within tile

    #pragma unroll 2
    for (int q = 0; q < Q_; ++q) {
        #pragma unroll
        for (int kh = 0; kh < 3; ++kh) {
            #pragma unroll
            for (int kw = 0; kw < 3; ++kw) {
                // adjacent rows: addresses repeat across kh -> ptxas CSEs the LDS
                const u64 x0 = xs2[q][ry + 0 + kh][px + kw];   // LDS.64 (2 ci)
                const u64 x1 = xs2[q][ry + 1 + kh][px + kw];
                const int tap = kh * 3 + kw;
                #pragma unroll
                for (int cp = 0; cp < CO_T / 2; ++cp) {
                    // one uniform LDS.128 fetches w for two co (each packed over ci-pair)
                    const ulonglong2 wv = *(const ulonglong2*)&ws2[q][tap][2 * cp];
                    u64 d0 = f2add(x0, wv.x);               // fma pipe
                    u64 d1 = f2add(x1, wv.x);
                    d0 &= 0x7fffffff7fffffffULL;            // alu pipe (2x LOP3)
                    d1 &= 0x7fffffff7fffffffULL;
                    acc[0][2 * cp + 0] = f2add(acc[0][2 * cp + 0], d0);
                    acc[1][2 * cp + 0] = f2add(acc[1][2 * cp + 0], d1);
                    u64 e0 = f2add(x0, wv.y);
                    u64 e1 = f2add(x1, wv.y);
                    e0 &= 0x7fffffff7fffffffULL;
                    e1 &= 0x7fffffff7fffffffULL;
                    acc[0][2 * cp + 1] = f2add(acc[0][2 * cp + 1], e0);
                    acc[1][2 * cp + 1] = f2add(acc[1][2 * cp + 1], e1);
                }
            }
        }
    }

    // ---- epilogue: horizontal add (even-ci + odd-ci), atomic combine (out pre-zeroed) ----
    #pragma unroll
    for (int co = 0; co < CO_T; ++co) {
        #pragma unroll
        for (int p = 0; p < 2; ++p) {
            const float s = u64lo(acc[p][co]) + u64hi(acc[p][co]);
            const int h = h0 + ry + p;
            atomicAdd(&out[(((size_t)n * CO_ + (co0 + co)) * H_ + h) * W_ + px], -s);
        }
    }
}

extern "C" void kernel_launch(void* const* d_in, const int* in_sizes, int n_in,
                              void* d_out, int out_size)
{
    const float* x = (const float*)d_in[0];
    const float* w = (const float*)d_in[1];
    float* out = (float*)d_out;

    const int N = in_sizes[0] / (CI_ * H_ * W_);   // 16

    cudaMemsetAsync(d_out, 0, (size_t)out_size * sizeof(float));

    dim3 grid(H_ / TILE_H, CO_ / CO_T, N * 8);     // (4, 8, 128) = 4096 blocks
    adder2d_kernel<<<grid, THREADS>>>(x, w, out);
}